// round 11
// baseline (speedup 1.0000x reference)
#include <cuda_runtime.h>
#include <cuda_pipeline_primitives.h>
#include <math.h>

#define BB 2
#define NN 512
#define CS 128
#define CH 16
#define HH 12
#define PQ 4
#define VV 8
#define HC (HH*CH)            /* 192 */
#define CATD (HH*(CH+VV*4))   /* 576 */

// ---------------- scratch (device globals; no allocations allowed) -----------
__device__ float q_g  [BB*HH*NN*CH];
__device__ float k_g  [BB*HH*NN*CH];
__device__ float v_g  [BB*HH*NN*CH];
__device__ float qp_g [BB*HH*NN*PQ*3];
__device__ float kp_g [BB*HH*NN*PQ*3];
__device__ float vp_g [BB*HH*NN*VV*3];
__device__ float sqq_g[BB*HH*NN];
__device__ float sqk_g[BB*HH*NN];
__device__ float cat_g[BB*NN*CATD];

// ---------------- kernel 1: projections (R3 version — best measured) --------
#define PR 4
__global__ __launch_bounds__(256) void proj_kernel(
    const float* __restrict__ s,  const float* __restrict__ R,
    const float* __restrict__ t,
    const float* __restrict__ Wq,  const float* __restrict__ bq,
    const float* __restrict__ Wkv, const float* __restrict__ bkv,
    const float* __restrict__ Wqp, const float* __restrict__ bqp,
    const float* __restrict__ Wkvp,const float* __restrict__ bkvp)
{
    __shared__ float s_sm[PR][CS];
    __shared__ float Rt_sm[PR][12];
    __shared__ float sqq_sm[PR][HH];
    __shared__ float sqk_sm[PR][HH];

    const int tid  = threadIdx.x;
    const int row0 = blockIdx.x * PR;

    for (int idx = tid; idx < PR*CS; idx += 256)
        s_sm[idx>>7][idx&127] = s[(long)row0*CS + idx];
    if (tid < PR*12) {
        int r = tid/12, c = tid%12;
        Rt_sm[r][c] = (c < 9) ? R[(long)(row0+r)*9 + c] : t[(long)(row0+r)*3 + (c-9)];
    }
    if (tid < PR*HH) {
        sqq_sm[tid/HH][tid%HH] = 0.f;
        sqk_sm[tid/HH][tid%HH] = 0.f;
    }
    __syncthreads();

    const int task = blockIdx.y*256 + tid;
    if (task < 768) {
        if (task < 576) {
            const float* W; float bias; int stride; int col;
            if (task < 192) { col = task;       W = Wq  + col; stride = HC;   bias = bq[col];  }
            else            { col = task - 192; W = Wkv + col; stride = 2*HC; bias = bkv[col]; }
            float acc[PR];
            #pragma unroll
            for (int r = 0; r < PR; r++) acc[r] = bias;
            #pragma unroll 16
            for (int k = 0; k < CS; k++) {
                float w = __ldg(&W[(long)k*stride]);
                #pragma unroll
                for (int r = 0; r < PR; r++) acc[r] += w * s_sm[r][k];
            }
            if (task < 192) {
                int h = col >> 4, c = col & 15;
                #pragma unroll
                for (int r = 0; r < PR; r++) {
                    int row = row0 + r, b = row >> 9, n = row & 511;
                    q_g[((long)(b*HH+h)*NN + n)*CH + c] = acc[r];
                }
            } else {
                int h = col >> 5, cc = col & 31;
                #pragma unroll
                for (int r = 0; r < PR; r++) {
                    int row = row0 + r, b = row >> 9, n = row & 511;
                    long base = ((long)(b*HH+h)*NN + n)*CH;
                    if (cc < 16) k_g[base + cc]        = acc[r];
                    else         v_g[base + (cc-16)]   = acc[r];
                }
            }
        } else {
            int p; const float* W; int npts; const float* bvec; int is_qp;
            if (task < 624) { p = task - 576; W = Wqp;  npts = 48;  bvec = bqp;  is_qp = 1; }
            else            { p = task - 624; W = Wkvp; npts = 144; bvec = bkvp; is_qp = 0; }
            float d0[PR], d1[PR], d2[PR];
            float b0 = bvec[0*npts+p], b1 = bvec[1*npts+p], b2 = bvec[2*npts+p];
            #pragma unroll
            for (int r = 0; r < PR; r++) { d0[r] = b0; d1[r] = b1; d2[r] = b2; }
            #pragma unroll 8
            for (int k = 0; k < CS; k++) {
                float w0 = __ldg(&W[(long)k*3*npts + 0*npts + p]);
                float w1 = __ldg(&W[(long)k*3*npts + 1*npts + p]);
                float w2 = __ldg(&W[(long)k*3*npts + 2*npts + p]);
                #pragma unroll
                for (int r = 0; r < PR; r++) {
                    float sv = s_sm[r][k];
                    d0[r] += w0*sv; d1[r] += w1*sv; d2[r] += w2*sv;
                }
            }
            #pragma unroll
            for (int r = 0; r < PR; r++) {
                int row = row0 + r, b = row >> 9, n = row & 511;
                float x0 = Rt_sm[r][0]*d0[r] + Rt_sm[r][1]*d1[r] + Rt_sm[r][2]*d2[r] + Rt_sm[r][9];
                float x1 = Rt_sm[r][3]*d0[r] + Rt_sm[r][4]*d1[r] + Rt_sm[r][5]*d2[r] + Rt_sm[r][10];
                float x2 = Rt_sm[r][6]*d0[r] + Rt_sm[r][7]*d1[r] + Rt_sm[r][8]*d2[r] + Rt_sm[r][11];
                if (is_qp) {
                    int h = p / PQ, pp = p % PQ;
                    long base = ((long)(b*HH+h)*NN + n)*(PQ*3) + pp*3;
                    qp_g[base+0] = x0; qp_g[base+1] = x1; qp_g[base+2] = x2;
                    atomicAdd(&sqq_sm[r][h], x0*x0 + x1*x1 + x2*x2);
                } else {
                    int h = p / (PQ+VV), idx = p % (PQ+VV);
                    if (idx < PQ) {
                        long base = ((long)(b*HH+h)*NN + n)*(PQ*3) + idx*3;
                        kp_g[base+0] = x0; kp_g[base+1] = x1; kp_g[base+2] = x2;
                        atomicAdd(&sqk_sm[r][h], x0*x0 + x1*x1 + x2*x2);
                    } else {
                        long base = ((long)(b*HH+h)*NN + n)*(VV*3) + (idx-PQ)*3;
                        vp_g[base+0] = x0; vp_g[base+1] = x1; vp_g[base+2] = x2;
                    }
                }
            }
        }
    }
    __syncthreads();
    if (blockIdx.y == 2 && tid < PR*HH) {
        int r = tid/HH, h = tid%HH;
        int row = row0 + r, b = row >> 9, n = row & 511;
        sqq_g[(long)(b*HH+h)*NN + n] = sqq_sm[r][h];
        sqk_g[(long)(b*HH+h)*NN + n] = sqk_sm[r][h];
    }
}

// ---------------- kernel 2: attention (R5 structure + split partial sums) ----
#define SKV 20   /* k/v tile stride in floats */
#define SKP 12   /* kp stride */
#define SVP 28   /* vp stride */
#define BUF 4096 /* float offset between buffers */

__global__ __launch_bounds__(256) void attn_kernel(
    const float* __restrict__ pair_mask,
    const float* __restrict__ R, const float* __restrict__ t,
    const float* __restrict__ head_weights)
{
    __shared__ __align__(16) float pool[2*BUF];   // 32 KB, double buffered
    __shared__ float red[8][2][41];

    const int tid  = threadIdx.x;
    const int lane = tid & 31;
    const int warp = tid >> 5;
    const int b = blockIdx.z, h = blockIdx.y;
    const int i0 = blockIdx.x*16 + warp*2;
    const int bh = b*HH + h;

    const float hwv = log1pf(__expf(head_weights[h])) * 0.1360827634879543f; // sqrt(1/54)
    const float c1  = -0.5f * hwv;
    const float qs  = 0.14433756729740643f;  // 1/sqrt(48)

    const float* kbase  = k_g  + (long)bh*NN*CH;
    const float* vbase  = v_g  + (long)bh*NN*CH;
    const float* kpbase = kp_g + (long)bh*NN*12;
    const float* vpbase = vp_g + (long)bh*NN*24;
    const float* sqkrow = sqk_g + (long)bh*NN;
    const float* mrow0  = pair_mask + ((long)b*NN + i0)*NN;
    const float* mrow1  = mrow0 + NN;

    float la0[16], la1[16];

    // ================= phase A: all logits =================
    {
        float q0[CH], q1[CH], qp0[12], qp1[12];
        {
            const float4* qr0 = (const float4*)(q_g + ((long)bh*NN + i0)*CH);
            const float4* qr1 = (const float4*)(q_g + ((long)bh*NN + i0+1)*CH);
            #pragma unroll
            for (int c = 0; c < 4; c++) {
                float4 a = qr0[c];
                q0[4*c]=a.x*qs; q0[4*c+1]=a.y*qs; q0[4*c+2]=a.z*qs; q0[4*c+3]=a.w*qs;
                float4 d = qr1[c];
                q1[4*c]=d.x*qs; q1[4*c+1]=d.y*qs; q1[4*c+2]=d.z*qs; q1[4*c+3]=d.w*qs;
            }
            const float4* pr0 = (const float4*)(qp_g + ((long)bh*NN + i0)*12);
            const float4* pr1 = (const float4*)(qp_g + ((long)bh*NN + i0+1)*12);
            #pragma unroll
            for (int c = 0; c < 3; c++) {
                float4 a = pr0[c];
                qp0[4*c]=a.x*hwv; qp0[4*c+1]=a.y*hwv; qp0[4*c+2]=a.z*hwv; qp0[4*c+3]=a.w*hwv;
                float4 d = pr1[c];
                qp1[4*c]=d.x*hwv; qp1[4*c+1]=d.y*hwv; qp1[4*c+2]=d.z*hwv; qp1[4*c+3]=d.w*hwv;
            }
        }
        const float base0 = c1 * __ldg(&sqq_g[(long)bh*NN + i0]);
        const float base1 = c1 * __ldg(&sqq_g[(long)bh*NN + i0+1]);

        // prologue fill jt=0 -> buf 0
        {
            const float4* k4  = (const float4*)kbase;
            for (int idx = tid; idx < 512; idx += 256)
                __pipeline_memcpy_async(&pool[(idx>>2)*SKV + ((idx&3)<<2)], &k4[idx], 16);
            const float4* kp4 = (const float4*)kpbase;
            for (int idx = tid; idx < 384; idx += 256) {
                int j = idx/3, c = idx - j*3;
                __pipeline_memcpy_async(&pool[2560 + j*SKP + (c<<2)], &kp4[idx], 16);
            }
        }
        __pipeline_commit();

        #pragma unroll
        for (int jt = 0; jt < 4; jt++) {
            if (jt < 3) {
                float* dst = pool + ((jt+1)&1)*BUF;
                const float4* k4  = (const float4*)(kbase + (jt+1)*128*CH);
                for (int idx = tid; idx < 512; idx += 256)
                    __pipeline_memcpy_async(&dst[(idx>>2)*SKV + ((idx&3)<<2)], &k4[idx], 16);
                const float4* kp4 = (const float4*)(kpbase + (jt+1)*128*12);
                for (int idx = tid; idx < 384; idx += 256) {
                    int j = idx/3, c = idx - j*3;
                    __pipeline_memcpy_async(&dst[2560 + j*SKP + (c<<2)], &kp4[idx], 16);
                }
                __pipeline_commit();
                __pipeline_wait_prior(1);
            } else {
                __pipeline_wait_prior(0);
            }
            __syncthreads();

            const float* ks  = pool + (jt&1)*BUF;
            const float* kps = ks + 2560;
            const int j0 = jt*128;
            #pragma unroll
            for (int u = 0; u < 4; u++) {
                const int j = u*32 + lane;
                // issue long-latency loads first (hide behind FMA chains)
                const float skraw = __ldg(&sqkrow[j0 + j]);
                const float m0    = __ldg(&mrow0[j0 + j]);
                const float m1    = __ldg(&mrow1[j0 + j]);
                const float4* k4  = (const float4*)(ks  + j*SKV);
                const float4* kp4 = (const float4*)(kps + j*SKP);
                // 4 independent partial chains per query (ILP 8 vs 2)
                float s0[4] = {0.f,0.f,0.f,0.f};
                float s1[4] = {0.f,0.f,0.f,0.f};
                #pragma unroll
                for (int c = 0; c < 4; c++) {
                    float4 kk = k4[c];
                    s0[c] += q0[4*c]*kk.x + q0[4*c+1]*kk.y + q0[4*c+2]*kk.z + q0[4*c+3]*kk.w;
                    s1[c] += q1[4*c]*kk.x + q1[4*c+1]*kk.y + q1[4*c+2]*kk.z + q1[4*c+3]*kk.w;
                }
                #pragma unroll
                for (int c = 0; c < 3; c++) {
                    float4 kk = kp4[c];
                    s0[c] += qp0[4*c]*kk.x + qp0[4*c+1]*kk.y + qp0[4*c+2]*kk.z + qp0[4*c+3]*kk.w;
                    s1[c] += qp1[4*c]*kk.x + qp1[4*c+1]*kk.y + qp1[4*c+2]*kk.z + qp1[4*c+3]*kk.w;
                }
                const float qk0 = (s0[0] + s0[1]) + (s0[2] + s0[3]);
                const float qk1 = (s1[0] + s1[1]) + (s1[2] + s1[3]);
                const float skc = c1 * skraw;
                la0[jt*4+u] = qk0 + skc + base0 + 100000.f*(m0 - 1.f);
                la1[jt*4+u] = qk1 + skc + base1 + 100000.f*(m1 - 1.f);
            }
            __syncthreads();
        }
    }

    // ================= exact softmax =================
    float ls0, ls1;
    {
        float M0 = la0[0], M1 = la1[0];
        #pragma unroll
        for (int x = 1; x < 16; x++) { M0 = fmaxf(M0, la0[x]); M1 = fmaxf(M1, la1[x]); }
        #pragma unroll
        for (int o = 16; o; o >>= 1) {
            M0 = fmaxf(M0, __shfl_xor_sync(0xffffffffu, M0, o));
            M1 = fmaxf(M1, __shfl_xor_sync(0xffffffffu, M1, o));
        }
        ls0 = 0.f; ls1 = 0.f;
        #pragma unroll
        for (int x = 0; x < 16; x++) {
            la0[x] = __expf(la0[x] - M0); ls0 += la0[x];
            la1[x] = __expf(la1[x] - M1); ls1 += la1[x];
        }
    }
    __syncthreads();   // phase A tiles dead before B refills pool

    // ================= phase B pass 1: o = A @ v =================
    {
        float av0[16], av1[16];
        #pragma unroll
        for (int x = 0; x < 16; x++) { av0[x] = 0.f; av1[x] = 0.f; }

        {
            const float4* v4 = (const float4*)vbase;
            for (int idx = tid; idx < 512; idx += 256)
                __pipeline_memcpy_async(&pool[(idx>>2)*SKV + ((idx&3)<<2)], &v4[idx], 16);
        }
        __pipeline_commit();

        #pragma unroll
        for (int jt = 0; jt < 4; jt++) {
            if (jt < 3) {
                float* dst = pool + ((jt+1)&1)*BUF;
                const float4* v4 = (const float4*)(vbase + (jt+1)*128*CH);
                for (int idx = tid; idx < 512; idx += 256)
                    __pipeline_memcpy_async(&dst[(idx>>2)*SKV + ((idx&3)<<2)], &v4[idx], 16);
                __pipeline_commit();
                __pipeline_wait_prior(1);
            } else {
                __pipeline_wait_prior(0);
            }
            __syncthreads();

            const float* vs = pool + (jt&1)*BUF;
            #pragma unroll
            for (int u = 0; u < 4; u++) {
                const int j = u*32 + lane;
                const float p0 = la0[jt*4+u];
                const float p1 = la1[jt*4+u];
                const float4* v4 = (const float4*)(vs + j*SKV);
                #pragma unroll
                for (int c = 0; c < 4; c++) {
                    float4 vv = v4[c];
                    av0[4*c]   += p0*vv.x; av0[4*c+1] += p0*vv.y;
                    av0[4*c+2] += p0*vv.z; av0[4*c+3] += p0*vv.w;
                    av1[4*c]   += p1*vv.x; av1[4*c+1] += p1*vv.y;
                    av1[4*c+2] += p1*vv.z; av1[4*c+3] += p1*vv.w;
                }
            }
            __syncthreads();
        }
        float lss = ls0;
        #pragma unroll
        for (int o = 16; o; o >>= 1) lss += __shfl_xor_sync(0xffffffffu, lss, o);
        if (lane == 0) red[warp][0][40] = lss;
        lss = ls1;
        #pragma unroll
        for (int o = 16; o; o >>= 1) lss += __shfl_xor_sync(0xffffffffu, lss, o);
        if (lane == 0) red[warp][1][40] = lss;
        #pragma unroll
        for (int x = 0; x < 16; x++) {
            float v0 = av0[x], v1 = av1[x];
            #pragma unroll
            for (int o = 16; o; o >>= 1) {
                v0 += __shfl_xor_sync(0xffffffffu, v0, o);
                v1 += __shfl_xor_sync(0xffffffffu, v1, o);
            }
            if (lane == 0) { red[warp][0][x] = v0; red[warp][1][x] = v1; }
        }
    }

    // ================= phase B pass 2: o_pt = A @ vp =================
    {
        float ap0[24], ap1[24];
        #pragma unroll
        for (int x = 0; x < 24; x++) { ap0[x] = 0.f; ap1[x] = 0.f; }

        {
            const float4* vp4 = (const float4*)vpbase;
            for (int idx = tid; idx < 768; idx += 256) {
                int j = idx/6, c = idx - j*6;
                __pipeline_memcpy_async(&pool[j*SVP + (c<<2)], &vp4[idx], 16);
            }
        }
        __pipeline_commit();

        #pragma unroll
        for (int jt = 0; jt < 4; jt++) {
            if (jt < 3) {
                float* dst = pool + ((jt+1)&1)*BUF;
                const float4* vp4 = (const float4*)(vpbase + (jt+1)*128*24);
                for (int idx = tid; idx < 768; idx += 256) {
                    int j = idx/6, c = idx - j*6;
                    __pipeline_memcpy_async(&dst[j*SVP + (c<<2)], &vp4[idx], 16);
                }
                __pipeline_commit();
                __pipeline_wait_prior(1);
            } else {
                __pipeline_wait_prior(0);
            }
            __syncthreads();

            const float* vps = pool + (jt&1)*BUF;
            #pragma unroll
            for (int u = 0; u < 4; u++) {
                const int j = u*32 + lane;
                const float p0 = la0[jt*4+u];
                const float p1 = la1[jt*4+u];
                const float4* vp4 = (const float4*)(vps + j*SVP);
                #pragma unroll
                for (int c = 0; c < 6; c++) {
                    float4 vv = vp4[c];
                    ap0[4*c]   += p0*vv.x; ap0[4*c+1] += p0*vv.y;
                    ap0[4*c+2] += p0*vv.z; ap0[4*c+3] += p0*vv.w;
                    ap1[4*c]   += p1*vv.x; ap1[4*c+1] += p1*vv.y;
                    ap1[4*c+2] += p1*vv.z; ap1[4*c+3] += p1*vv.w;
                }
            }
            __syncthreads();
        }
        #pragma unroll
        for (int x = 0; x < 24; x++) {
            float v0 = ap0[x], v1 = ap1[x];
            #pragma unroll
            for (int o = 16; o; o >>= 1) {
                v0 += __shfl_xor_sync(0xffffffffu, v0, o);
                v1 += __shfl_xor_sync(0xffffffffu, v1, o);
            }
            if (lane == 0) { red[warp][0][16+x] = v0; red[warp][1][16+x] = v1; }
        }
    }
    __syncwarp();

    // ================= finalize =================
    #pragma unroll
    for (int ii = 0; ii < 2; ii++) {
        const int i = i0 + ii;
        const float sinv = 1.f / red[warp][ii][40];
        const long rowbase = ((long)(b*NN + i))*CATD;
        if (lane < 16) {
            cat_g[rowbase + h*CH + lane] = red[warp][ii][lane] * sinv;
        } else if (lane < 24) {
            const int vv = lane - 16;
            float gx = red[warp][ii][16 + vv*3 + 0] * sinv;
            float gy = red[warp][ii][16 + vv*3 + 1] * sinv;
            float gz = red[warp][ii][16 + vv*3 + 2] * sinv;
            const float* Rr = R + ((long)(b*NN + i))*9;
            const float* tr = t + ((long)(b*NN + i))*3;
            float lx = Rr[0]*gx + Rr[3]*gy + Rr[6]*gz - tr[0];
            float ly = Rr[1]*gx + Rr[4]*gy + Rr[7]*gz - tr[1];
            float lz = Rr[2]*gx + Rr[5]*gy + Rr[8]*gz - tr[2];
            float nrm = sqrtf(lx*lx + ly*ly + lz*lz + 1e-8f);
            cat_g[rowbase + HC +   0 + h*VV + vv] = lx;
            cat_g[rowbase + HC +  96 + h*VV + vv] = ly;
            cat_g[rowbase + HC + 192 + h*VV + vv] = lz;
            cat_g[rowbase + HC + 288 + h*VV + vv] = nrm;
        }
    }
}

// ---------------- kernel 3: output projection (8 rows/block) -----------------
__global__ __launch_bounds__(256) void out_kernel(
    const float* __restrict__ Wout, const float* __restrict__ bout,
    float* __restrict__ out)
{
    __shared__ float csm[8*CATD];
    const int tid  = threadIdx.x;
    const int col  = tid & 127;
    const int half = tid >> 7;
    const int row0 = blockIdx.x * 8;

    for (int idx = tid; idx < 8*CATD; idx += 256)
        csm[idx] = cat_g[(long)row0*CATD + idx];
    __syncthreads();

    float acc[4] = {0.f, 0.f, 0.f, 0.f};
    const float* cb = csm + half*4*CATD;
    #pragma unroll 8
    for (int k = 0; k < CATD; k++) {
        float w = __ldg(&Wout[(long)k*CS + col]);
        #pragma unroll
        for (int r = 0; r < 4; r++) acc[r] += cb[r*CATD + k] * w;
    }
    float bb = bout[col];
    #pragma unroll
    for (int r = 0; r < 4; r++)
        out[(long)(row0 + half*4 + r)*CS + col] = acc[r] + bb;
}

// ---------------- launcher ----------------------------------------------------
extern "C" void kernel_launch(void* const* d_in, const int* in_sizes, int n_in,
                              void* d_out, int out_size)
{
    const float* s    = (const float*)d_in[0];
    const float* R    = (const float*)d_in[1];
    const float* t    = (const float*)d_in[2];
    const float* mask = (const float*)d_in[3];
    const float* Wq   = (const float*)d_in[4];
    const float* bq   = (const float*)d_in[5];
    const float* Wkv  = (const float*)d_in[6];
    const float* bkv  = (const float*)d_in[7];
    const float* Wqp  = (const float*)d_in[8];
    const float* bqp  = (const float*)d_in[9];
    const float* Wkvp = (const float*)d_in[10];
    const float* bkvp = (const float*)d_in[11];
    const float* hwts = (const float*)d_in[12];
    const float* Wout = (const float*)d_in[13];
    const float* bout = (const float*)d_in[14];
    float* out = (float*)d_out;

    proj_kernel<<<dim3((BB*NN)/PR, 3), 256>>>(s, R, t, Wq, bq, Wkv, bkv, Wqp, bqp, Wkvp, bkvp);
    attn_kernel<<<dim3(NN/16, HH, BB), 256>>>(mask, R, t, hwts);
    out_kernel<<<(BB*NN)/8, 256>>>(Wout, bout, out);
}

// round 12
// speedup vs baseline: 1.1105x; 1.1105x over previous
#include <cuda_runtime.h>
#include <cuda_pipeline_primitives.h>
#include <math.h>

#define BB 2
#define NN 512
#define CS 128
#define CH 16
#define HH 12
#define PQ 4
#define VV 8
#define HC (HH*CH)            /* 192 */
#define CATD (HH*(CH+VV*4))   /* 576 */

// ---------------- scratch (device globals; no allocations allowed) -----------
__device__ float q_g  [BB*HH*NN*CH];
__device__ float k_g  [BB*HH*NN*CH];
__device__ float v_g  [BB*HH*NN*CH];
__device__ float qp_g [BB*HH*NN*PQ*3];
__device__ float kp_g [BB*HH*NN*PQ*3];
__device__ float vp_g [BB*HH*NN*VV*3];
__device__ float sqq_g[BB*HH*NN];
__device__ float sqk_g[BB*HH*NN];
__device__ float cat_g[BB*NN*CATD];

// ---------------- kernel 1: projections (R3 version — best measured) --------
#define PR 4
__global__ __launch_bounds__(256) void proj_kernel(
    const float* __restrict__ s,  const float* __restrict__ R,
    const float* __restrict__ t,
    const float* __restrict__ Wq,  const float* __restrict__ bq,
    const float* __restrict__ Wkv, const float* __restrict__ bkv,
    const float* __restrict__ Wqp, const float* __restrict__ bqp,
    const float* __restrict__ Wkvp,const float* __restrict__ bkvp)
{
    __shared__ float s_sm[PR][CS];
    __shared__ float Rt_sm[PR][12];
    __shared__ float sqq_sm[PR][HH];
    __shared__ float sqk_sm[PR][HH];

    const int tid  = threadIdx.x;
    const int row0 = blockIdx.x * PR;

    for (int idx = tid; idx < PR*CS; idx += 256)
        s_sm[idx>>7][idx&127] = s[(long)row0*CS + idx];
    if (tid < PR*12) {
        int r = tid/12, c = tid%12;
        Rt_sm[r][c] = (c < 9) ? R[(long)(row0+r)*9 + c] : t[(long)(row0+r)*3 + (c-9)];
    }
    if (tid < PR*HH) {
        sqq_sm[tid/HH][tid%HH] = 0.f;
        sqk_sm[tid/HH][tid%HH] = 0.f;
    }
    __syncthreads();

    const int task = blockIdx.y*256 + tid;
    if (task < 768) {
        if (task < 576) {
            const float* W; float bias; int stride; int col;
            if (task < 192) { col = task;       W = Wq  + col; stride = HC;   bias = bq[col];  }
            else            { col = task - 192; W = Wkv + col; stride = 2*HC; bias = bkv[col]; }
            float acc[PR];
            #pragma unroll
            for (int r = 0; r < PR; r++) acc[r] = bias;
            #pragma unroll 16
            for (int k = 0; k < CS; k++) {
                float w = __ldg(&W[(long)k*stride]);
                #pragma unroll
                for (int r = 0; r < PR; r++) acc[r] += w * s_sm[r][k];
            }
            if (task < 192) {
                int h = col >> 4, c = col & 15;
                #pragma unroll
                for (int r = 0; r < PR; r++) {
                    int row = row0 + r, b = row >> 9, n = row & 511;
                    q_g[((long)(b*HH+h)*NN + n)*CH + c] = acc[r];
                }
            } else {
                int h = col >> 5, cc = col & 31;
                #pragma unroll
                for (int r = 0; r < PR; r++) {
                    int row = row0 + r, b = row >> 9, n = row & 511;
                    long base = ((long)(b*HH+h)*NN + n)*CH;
                    if (cc < 16) k_g[base + cc]        = acc[r];
                    else         v_g[base + (cc-16)]   = acc[r];
                }
            }
        } else {
            int p; const float* W; int npts; const float* bvec; int is_qp;
            if (task < 624) { p = task - 576; W = Wqp;  npts = 48;  bvec = bqp;  is_qp = 1; }
            else            { p = task - 624; W = Wkvp; npts = 144; bvec = bkvp; is_qp = 0; }
            float d0[PR], d1[PR], d2[PR];
            float b0 = bvec[0*npts+p], b1 = bvec[1*npts+p], b2 = bvec[2*npts+p];
            #pragma unroll
            for (int r = 0; r < PR; r++) { d0[r] = b0; d1[r] = b1; d2[r] = b2; }
            #pragma unroll 8
            for (int k = 0; k < CS; k++) {
                float w0 = __ldg(&W[(long)k*3*npts + 0*npts + p]);
                float w1 = __ldg(&W[(long)k*3*npts + 1*npts + p]);
                float w2 = __ldg(&W[(long)k*3*npts + 2*npts + p]);
                #pragma unroll
                for (int r = 0; r < PR; r++) {
                    float sv = s_sm[r][k];
                    d0[r] += w0*sv; d1[r] += w1*sv; d2[r] += w2*sv;
                }
            }
            #pragma unroll
            for (int r = 0; r < PR; r++) {
                int row = row0 + r, b = row >> 9, n = row & 511;
                float x0 = Rt_sm[r][0]*d0[r] + Rt_sm[r][1]*d1[r] + Rt_sm[r][2]*d2[r] + Rt_sm[r][9];
                float x1 = Rt_sm[r][3]*d0[r] + Rt_sm[r][4]*d1[r] + Rt_sm[r][5]*d2[r] + Rt_sm[r][10];
                float x2 = Rt_sm[r][6]*d0[r] + Rt_sm[r][7]*d1[r] + Rt_sm[r][8]*d2[r] + Rt_sm[r][11];
                if (is_qp) {
                    int h = p / PQ, pp = p % PQ;
                    long base = ((long)(b*HH+h)*NN + n)*(PQ*3) + pp*3;
                    qp_g[base+0] = x0; qp_g[base+1] = x1; qp_g[base+2] = x2;
                    atomicAdd(&sqq_sm[r][h], x0*x0 + x1*x1 + x2*x2);
                } else {
                    int h = p / (PQ+VV), idx = p % (PQ+VV);
                    if (idx < PQ) {
                        long base = ((long)(b*HH+h)*NN + n)*(PQ*3) + idx*3;
                        kp_g[base+0] = x0; kp_g[base+1] = x1; kp_g[base+2] = x2;
                        atomicAdd(&sqk_sm[r][h], x0*x0 + x1*x1 + x2*x2);
                    } else {
                        long base = ((long)(b*HH+h)*NN + n)*(VV*3) + (idx-PQ)*3;
                        vp_g[base+0] = x0; vp_g[base+1] = x1; vp_g[base+2] = x2;
                    }
                }
            }
        }
    }
    __syncthreads();
    if (blockIdx.y == 2 && tid < PR*HH) {
        int r = tid/HH, h = tid%HH;
        int row = row0 + r, b = row >> 9, n = row & 511;
        sqq_g[(long)(b*HH+h)*NN + n] = sqq_sm[r][h];
        sqk_g[(long)(b*HH+h)*NN + n] = sqk_sm[r][h];
    }
}

// ---------------- kernel 2: attention (R5-exact structure, fmaf mask) --------
#define SKV 20   /* k/v tile stride in floats */
#define SKP 12   /* kp stride */
#define SVP 28   /* vp stride */
#define BUF 4096 /* float offset between buffers */

__global__ __launch_bounds__(256) void attn_kernel(
    const float* __restrict__ pair_mask,
    const float* __restrict__ R, const float* __restrict__ t,
    const float* __restrict__ head_weights)
{
    __shared__ __align__(16) float pool[2*BUF];   // 32 KB, double buffered
    __shared__ float red[8][2][41];

    const int tid  = threadIdx.x;
    const int lane = tid & 31;
    const int warp = tid >> 5;
    const int b = blockIdx.z, h = blockIdx.y;
    const int i0 = blockIdx.x*16 + warp*2;
    const int bh = b*HH + h;

    const float hwv = log1pf(__expf(head_weights[h])) * 0.1360827634879543f; // sqrt(1/54)
    const float c1  = -0.5f * hwv;
    const float qs  = 0.14433756729740643f;  // 1/sqrt(48)

    const float* kbase  = k_g  + (long)bh*NN*CH;
    const float* vbase  = v_g  + (long)bh*NN*CH;
    const float* kpbase = kp_g + (long)bh*NN*12;
    const float* vpbase = vp_g + (long)bh*NN*24;
    const float* sqkrow = sqk_g + (long)bh*NN;
    const float* mrow0  = pair_mask + ((long)b*NN + i0)*NN;
    const float* mrow1  = mrow0 + NN;

    float la0[16], la1[16];

    // ================= phase A: all logits =================
    {
        float q0[CH], q1[CH], qp0[12], qp1[12];
        {
            const float4* qr0 = (const float4*)(q_g + ((long)bh*NN + i0)*CH);
            const float4* qr1 = (const float4*)(q_g + ((long)bh*NN + i0+1)*CH);
            #pragma unroll
            for (int c = 0; c < 4; c++) {
                float4 a = qr0[c];
                q0[4*c]=a.x*qs; q0[4*c+1]=a.y*qs; q0[4*c+2]=a.z*qs; q0[4*c+3]=a.w*qs;
                float4 d = qr1[c];
                q1[4*c]=d.x*qs; q1[4*c+1]=d.y*qs; q1[4*c+2]=d.z*qs; q1[4*c+3]=d.w*qs;
            }
            const float4* pr0 = (const float4*)(qp_g + ((long)bh*NN + i0)*12);
            const float4* pr1 = (const float4*)(qp_g + ((long)bh*NN + i0+1)*12);
            #pragma unroll
            for (int c = 0; c < 3; c++) {
                float4 a = pr0[c];
                qp0[4*c]=a.x*hwv; qp0[4*c+1]=a.y*hwv; qp0[4*c+2]=a.z*hwv; qp0[4*c+3]=a.w*hwv;
                float4 d = pr1[c];
                qp1[4*c]=d.x*hwv; qp1[4*c+1]=d.y*hwv; qp1[4*c+2]=d.z*hwv; qp1[4*c+3]=d.w*hwv;
            }
        }
        const float base0 = c1 * __ldg(&sqq_g[(long)bh*NN + i0]);
        const float base1 = c1 * __ldg(&sqq_g[(long)bh*NN + i0+1]);

        // prologue fill jt=0 -> buf 0
        {
            const float4* k4  = (const float4*)kbase;
            for (int idx = tid; idx < 512; idx += 256)
                __pipeline_memcpy_async(&pool[(idx>>2)*SKV + ((idx&3)<<2)], &k4[idx], 16);
            const float4* kp4 = (const float4*)kpbase;
            for (int idx = tid; idx < 384; idx += 256) {
                int j = idx/3, c = idx - j*3;
                __pipeline_memcpy_async(&pool[2560 + j*SKP + (c<<2)], &kp4[idx], 16);
            }
        }
        __pipeline_commit();

        #pragma unroll
        for (int jt = 0; jt < 4; jt++) {
            if (jt < 3) {
                float* dst = pool + ((jt+1)&1)*BUF;
                const float4* k4  = (const float4*)(kbase + (jt+1)*128*CH);
                for (int idx = tid; idx < 512; idx += 256)
                    __pipeline_memcpy_async(&dst[(idx>>2)*SKV + ((idx&3)<<2)], &k4[idx], 16);
                const float4* kp4 = (const float4*)(kpbase + (jt+1)*128*12);
                for (int idx = tid; idx < 384; idx += 256) {
                    int j = idx/3, c = idx - j*3;
                    __pipeline_memcpy_async(&dst[2560 + j*SKP + (c<<2)], &kp4[idx], 16);
                }
                __pipeline_commit();
                __pipeline_wait_prior(1);
            } else {
                __pipeline_wait_prior(0);
            }
            __syncthreads();

            const float* ks  = pool + (jt&1)*BUF;
            const float* kps = ks + 2560;
            const int j0 = jt*128;
            #pragma unroll
            for (int u = 0; u < 4; u++) {
                const int j = u*32 + lane;
                const float4* k4  = (const float4*)(ks  + j*SKV);
                const float4* kp4 = (const float4*)(kps + j*SKP);
                float qk0 = 0.f, qk1 = 0.f;
                #pragma unroll
                for (int c = 0; c < 4; c++) {
                    float4 kk = k4[c];
                    qk0 += q0[4*c]*kk.x + q0[4*c+1]*kk.y + q0[4*c+2]*kk.z + q0[4*c+3]*kk.w;
                    qk1 += q1[4*c]*kk.x + q1[4*c+1]*kk.y + q1[4*c+2]*kk.z + q1[4*c+3]*kk.w;
                }
                #pragma unroll
                for (int c = 0; c < 3; c++) {
                    float4 kk = kp4[c];
                    qk0 += qp0[4*c]*kk.x + qp0[4*c+1]*kk.y + qp0[4*c+2]*kk.z + qp0[4*c+3]*kk.w;
                    qk1 += qp1[4*c]*kk.x + qp1[4*c+1]*kk.y + qp1[4*c+2]*kk.z + qp1[4*c+3]*kk.w;
                }
                const float skc = c1 * __ldg(&sqkrow[j0 + j]);
                // exact masked offset: fmaf gives exactly 0.0 when mask==1
                const float mq0 = fmaf(__ldg(&mrow0[j0 + j]), 100000.f, -100000.f);
                const float mq1 = fmaf(__ldg(&mrow1[j0 + j]), 100000.f, -100000.f);
                la0[jt*4+u] = qk0 + skc + base0 + mq0;
                la1[jt*4+u] = qk1 + skc + base1 + mq1;
            }
            __syncthreads();
        }
    }

    // ================= exact softmax =================
    float ls0, ls1;
    {
        float M0 = la0[0], M1 = la1[0];
        #pragma unroll
        for (int x = 1; x < 16; x++) { M0 = fmaxf(M0, la0[x]); M1 = fmaxf(M1, la1[x]); }
        #pragma unroll
        for (int o = 16; o; o >>= 1) {
            M0 = fmaxf(M0, __shfl_xor_sync(0xffffffffu, M0, o));
            M1 = fmaxf(M1, __shfl_xor_sync(0xffffffffu, M1, o));
        }
        ls0 = 0.f; ls1 = 0.f;
        #pragma unroll
        for (int x = 0; x < 16; x++) {
            la0[x] = __expf(la0[x] - M0); ls0 += la0[x];
            la1[x] = __expf(la1[x] - M1); ls1 += la1[x];
        }
    }
    __syncthreads();   // phase A tiles dead before B refills pool

    // ================= phase B pass 1: o = A @ v =================
    {
        float av0[16], av1[16];
        #pragma unroll
        for (int x = 0; x < 16; x++) { av0[x] = 0.f; av1[x] = 0.f; }

        {
            const float4* v4 = (const float4*)vbase;
            for (int idx = tid; idx < 512; idx += 256)
                __pipeline_memcpy_async(&pool[(idx>>2)*SKV + ((idx&3)<<2)], &v4[idx], 16);
        }
        __pipeline_commit();

        #pragma unroll
        for (int jt = 0; jt < 4; jt++) {
            if (jt < 3) {
                float* dst = pool + ((jt+1)&1)*BUF;
                const float4* v4 = (const float4*)(vbase + (jt+1)*128*CH);
                for (int idx = tid; idx < 512; idx += 256)
                    __pipeline_memcpy_async(&dst[(idx>>2)*SKV + ((idx&3)<<2)], &v4[idx], 16);
                __pipeline_commit();
                __pipeline_wait_prior(1);
            } else {
                __pipeline_wait_prior(0);
            }
            __syncthreads();

            const float* vs = pool + (jt&1)*BUF;
            #pragma unroll
            for (int u = 0; u < 4; u++) {
                const int j = u*32 + lane;
                const float p0 = la0[jt*4+u];
                const float p1 = la1[jt*4+u];
                const float4* v4 = (const float4*)(vs + j*SKV);
                #pragma unroll
                for (int c = 0; c < 4; c++) {
                    float4 vv = v4[c];
                    av0[4*c]   += p0*vv.x; av0[4*c+1] += p0*vv.y;
                    av0[4*c+2] += p0*vv.z; av0[4*c+3] += p0*vv.w;
                    av1[4*c]   += p1*vv.x; av1[4*c+1] += p1*vv.y;
                    av1[4*c+2] += p1*vv.z; av1[4*c+3] += p1*vv.w;
                }
            }
            __syncthreads();
        }
        float lss = ls0;
        #pragma unroll
        for (int o = 16; o; o >>= 1) lss += __shfl_xor_sync(0xffffffffu, lss, o);
        if (lane == 0) red[warp][0][40] = lss;
        lss = ls1;
        #pragma unroll
        for (int o = 16; o; o >>= 1) lss += __shfl_xor_sync(0xffffffffu, lss, o);
        if (lane == 0) red[warp][1][40] = lss;
        #pragma unroll
        for (int x = 0; x < 16; x++) {
            float v0 = av0[x], v1 = av1[x];
            #pragma unroll
            for (int o = 16; o; o >>= 1) {
                v0 += __shfl_xor_sync(0xffffffffu, v0, o);
                v1 += __shfl_xor_sync(0xffffffffu, v1, o);
            }
            if (lane == 0) { red[warp][0][x] = v0; red[warp][1][x] = v1; }
        }
    }

    // ================= phase B pass 2: o_pt = A @ vp =================
    {
        float ap0[24], ap1[24];
        #pragma unroll
        for (int x = 0; x < 24; x++) { ap0[x] = 0.f; ap1[x] = 0.f; }

        {
            const float4* vp4 = (const float4*)vpbase;
            for (int idx = tid; idx < 768; idx += 256) {
                int j = idx/6, c = idx - j*6;
                __pipeline_memcpy_async(&pool[j*SVP + (c<<2)], &vp4[idx], 16);
            }
        }
        __pipeline_commit();

        #pragma unroll
        for (int jt = 0; jt < 4; jt++) {
            if (jt < 3) {
                float* dst = pool + ((jt+1)&1)*BUF;
                const float4* vp4 = (const float4*)(vpbase + (jt+1)*128*24);
                for (int idx = tid; idx < 768; idx += 256) {
                    int j = idx/6, c = idx - j*6;
                    __pipeline_memcpy_async(&dst[j*SVP + (c<<2)], &vp4[idx], 16);
                }
                __pipeline_commit();
                __pipeline_wait_prior(1);
            } else {
                __pipeline_wait_prior(0);
            }
            __syncthreads();

            const float* vps = pool + (jt&1)*BUF;
            #pragma unroll
            for (int u = 0; u < 4; u++) {
                const int j = u*32 + lane;
                const float p0 = la0[jt*4+u];
                const float p1 = la1[jt*4+u];
                const float4* vp4 = (const float4*)(vps + j*SVP);
                #pragma unroll
                for (int c = 0; c < 6; c++) {
                    float4 vv = vp4[c];
                    ap0[4*c]   += p0*vv.x; ap0[4*c+1] += p0*vv.y;
                    ap0[4*c+2] += p0*vv.z; ap0[4*c+3] += p0*vv.w;
                    ap1[4*c]   += p1*vv.x; ap1[4*c+1] += p1*vv.y;
                    ap1[4*c+2] += p1*vv.z; ap1[4*c+3] += p1*vv.w;
                }
            }
            __syncthreads();
        }
        #pragma unroll
        for (int x = 0; x < 24; x++) {
            float v0 = ap0[x], v1 = ap1[x];
            #pragma unroll
            for (int o = 16; o; o >>= 1) {
                v0 += __shfl_xor_sync(0xffffffffu, v0, o);
                v1 += __shfl_xor_sync(0xffffffffu, v1, o);
            }
            if (lane == 0) { red[warp][0][16+x] = v0; red[warp][1][16+x] = v1; }
        }
    }
    __syncwarp();

    // ================= finalize =================
    #pragma unroll
    for (int ii = 0; ii < 2; ii++) {
        const int i = i0 + ii;
        const float sinv = 1.f / red[warp][ii][40];
        const long rowbase = ((long)(b*NN + i))*CATD;
        if (lane < 16) {
            cat_g[rowbase + h*CH + lane] = red[warp][ii][lane] * sinv;
        } else if (lane < 24) {
            const int vv = lane - 16;
            float gx = red[warp][ii][16 + vv*3 + 0] * sinv;
            float gy = red[warp][ii][16 + vv*3 + 1] * sinv;
            float gz = red[warp][ii][16 + vv*3 + 2] * sinv;
            const float* Rr = R + ((long)(b*NN + i))*9;
            const float* tr = t + ((long)(b*NN + i))*3;
            float lx = Rr[0]*gx + Rr[3]*gy + Rr[6]*gz - tr[0];
            float ly = Rr[1]*gx + Rr[4]*gy + Rr[7]*gz - tr[1];
            float lz = Rr[2]*gx + Rr[5]*gy + Rr[8]*gz - tr[2];
            float nrm = sqrtf(lx*lx + ly*ly + lz*lz + 1e-8f);
            cat_g[rowbase + HC +   0 + h*VV + vv] = lx;
            cat_g[rowbase + HC +  96 + h*VV + vv] = ly;
            cat_g[rowbase + HC + 192 + h*VV + vv] = lz;
            cat_g[rowbase + HC + 288 + h*VV + vv] = nrm;
        }
    }
}

// ---------------- kernel 3: output projection (8 rows/block) -----------------
__global__ __launch_bounds__(256) void out_kernel(
    const float* __restrict__ Wout, const float* __restrict__ bout,
    float* __restrict__ out)
{
    __shared__ float csm[8*CATD];
    const int tid  = threadIdx.x;
    const int col  = tid & 127;
    const int half = tid >> 7;
    const int row0 = blockIdx.x * 8;

    for (int idx = tid; idx < 8*CATD; idx += 256)
        csm[idx] = cat_g[(long)row0*CATD + idx];
    __syncthreads();

    float acc[4] = {0.f, 0.f, 0.f, 0.f};
    const float* cb = csm + half*4*CATD;
    #pragma unroll 8
    for (int k = 0; k < CATD; k++) {
        float w = __ldg(&Wout[(long)k*CS + col]);
        #pragma unroll
        for (int r = 0; r < 4; r++) acc[r] += cb[r*CATD + k] * w;
    }
    float bb = bout[col];
    #pragma unroll
    for (int r = 0; r < 4; r++)
        out[(long)(row0 + half*4 + r)*CS + col] = acc[r] + bb;
}

// ---------------- launcher ----------------------------------------------------
extern "C" void kernel_launch(void* const* d_in, const int* in_sizes, int n_in,
                              void* d_out, int out_size)
{
    const float* s    = (const float*)d_in[0];
    const float* R    = (const float*)d_in[1];
    const float* t    = (const float*)d_in[2];
    const float* mask = (const float*)d_in[3];
    const float* Wq   = (const float*)d_in[4];
    const float* bq   = (const float*)d_in[5];
    const float* Wkv  = (const float*)d_in[6];
    const float* bkv  = (const float*)d_in[7];
    const float* Wqp  = (const float*)d_in[8];
    const float* bqp  = (const float*)d_in[9];
    const float* Wkvp = (const float*)d_in[10];
    const float* bkvp = (const float*)d_in[11];
    const float* hwts = (const float*)d_in[12];
    const float* Wout = (const float*)d_in[13];
    const float* bout = (const float*)d_in[14];
    float* out = (float*)d_out;

    proj_kernel<<<dim3((BB*NN)/PR, 3), 256>>>(s, R, t, Wq, bq, Wkv, bkv, Wqp, bqp, Wkvp, bkvp);
    attn_kernel<<<dim3(NN/16, HH, BB), 256>>>(mask, R, t, hwts);
    out_kernel<<<(BB*NN)/8, 256>>>(Wout, bout, out);
}

// round 13
// speedup vs baseline: 1.1503x; 1.0358x over previous
#include <cuda_runtime.h>
#include <cuda_pipeline_primitives.h>
#include <math.h>

#define BB 2
#define NN 512
#define CS 128
#define CH 16
#define HH 12
#define PQ 4
#define VV 8
#define HC (HH*CH)            /* 192 */
#define CATD (HH*(CH+VV*4))   /* 576 */

// ---------------- scratch (device globals; no allocations allowed) -----------
__device__ float q_g  [BB*HH*NN*CH];
__device__ float k_g  [BB*HH*NN*CH];
__device__ float v_g  [BB*HH*NN*CH];
__device__ float qp_g [BB*HH*NN*PQ*3];
__device__ float kp_g [BB*HH*NN*PQ*3];
__device__ float vp_g [BB*HH*NN*VV*3];
__device__ float sqq_g[BB*HH*NN];
__device__ float sqk_g[BB*HH*NN];
__device__ float cat_g[BB*NN*CATD];

// ---------------- kernel 1: projections — cp.async W-staged GEMM -------------
// 128 blocks x 288 threads; 8 rows/block; thread owns 4 unified cols (1152 wide).
// W staged in 16 chunks of 8 k-rows, double buffered.
#define PRJ 8
#define NCOL 1152
// dynamic smem layout (floats):
#define S_OFF   0        /* s rows as float4: PRJ*128 floats            */
#define RAW_OFF 1024     /* raw point projections: PRJ*576              */
#define RT_OFF  5632     /* Rt: PRJ*12                                  */
#define SQQ_OFF 5728     /* PRJ*12 */
#define SQK_OFF 5824     /* PRJ*12 */
#define W_OFF   5952     /* 2 buffers x 8*1152 floats                   */
#define PROJ_SMEM_FLOATS (W_OFF + 2*8*NCOL)
#define PROJ_SMEM_BYTES  (PROJ_SMEM_FLOATS*4)

__global__ __launch_bounds__(288) void proj_kernel(
    const float* __restrict__ s,  const float* __restrict__ R,
    const float* __restrict__ t,
    const float* __restrict__ Wq,  const float* __restrict__ bq,
    const float* __restrict__ Wkv, const float* __restrict__ bkv,
    const float* __restrict__ Wqp, const float* __restrict__ bqp,
    const float* __restrict__ Wkvp,const float* __restrict__ bkvp)
{
    extern __shared__ __align__(16) float psm[];
    const int tid  = threadIdx.x;
    const int row0 = blockIdx.x * PRJ;

    // ---- stage s rows, frames, zero norm accumulators ----
    for (int idx = tid; idx < PRJ*CS/4; idx += 288)
        ((float4*)(psm + S_OFF))[idx] = ((const float4*)s)[(long)row0*32 + idx];
    if (tid < PRJ*12) {
        int r = tid/12, c = tid%12;
        psm[RT_OFF + r*12 + c] =
            (c < 9) ? R[(long)(row0+r)*9 + c] : t[(long)(row0+r)*3 + (c-9)];
    }
    if (tid < PRJ*HH) {
        psm[SQQ_OFF + tid] = 0.f;
        psm[SQK_OFF + tid] = 0.f;
    }

    // ---- column ownership ----
    const int col = tid * 4;           // 0..1148
    const float* Wb; const float* bb; int stride; int lcol;
    if (col < 192)      { Wb = Wq;   bb = bq;   stride = 192; lcol = col;       }
    else if (col < 576) { Wb = Wkv;  bb = bkv;  stride = 384; lcol = col - 192; }
    else if (col < 720) { Wb = Wqp;  bb = bqp;  stride = 144; lcol = col - 576; }
    else                { Wb = Wkvp; bb = bkvp; stride = 432; lcol = col - 720; }

    // ---- prologue: stage W chunk 0 (k = 0..7) ----
    {
        float* dst = psm + W_OFF;
        #pragma unroll
        for (int k = 0; k < 8; k++)
            __pipeline_memcpy_async(&dst[k*NCOL + col], Wb + (long)k*stride + lcol, 16);
    }
    __pipeline_commit();

    const float4 bias4 = __ldg((const float4*)(bb + lcol));
    float4 acc[PRJ];
    #pragma unroll
    for (int r = 0; r < PRJ; r++) acc[r] = bias4;

    __syncthreads();   // s rows staged before use

    // ---- main loop: 16 chunks of 8 k ----
    for (int ch = 0; ch < 16; ch++) {
        if (ch < 15) {
            float* dst = psm + W_OFF + ((ch+1)&1)*(8*NCOL);
            const long kbase = (long)(ch+1)*8;
            #pragma unroll
            for (int k = 0; k < 8; k++)
                __pipeline_memcpy_async(&dst[k*NCOL + col],
                                        Wb + (kbase+k)*stride + lcol, 16);
            __pipeline_commit();
            __pipeline_wait_prior(1);
        } else {
            __pipeline_wait_prior(0);
        }
        __syncthreads();

        const float* Wc = psm + W_OFF + (ch&1)*(8*NCOL);
        const float4* s4 = (const float4*)(psm + S_OFF);
        #pragma unroll
        for (int kq = 0; kq < 2; kq++) {
            float4 w0 = *(const float4*)&Wc[(kq*4+0)*NCOL + col];
            float4 w1 = *(const float4*)&Wc[(kq*4+1)*NCOL + col];
            float4 w2 = *(const float4*)&Wc[(kq*4+2)*NCOL + col];
            float4 w3 = *(const float4*)&Wc[(kq*4+3)*NCOL + col];
            #pragma unroll
            for (int r = 0; r < PRJ; r++) {
                float4 sv = s4[r*32 + ch*2 + kq];
                acc[r].x += w0.x*sv.x + w1.x*sv.y + w2.x*sv.z + w3.x*sv.w;
                acc[r].y += w0.y*sv.x + w1.y*sv.y + w2.y*sv.z + w3.y*sv.w;
                acc[r].z += w0.z*sv.x + w1.z*sv.y + w2.z*sv.z + w3.z*sv.w;
                acc[r].w += w0.w*sv.x + w1.w*sv.y + w2.w*sv.z + w3.w*sv.w;
            }
        }
        __syncthreads();
    }

    // ---- scatter results ----
    if (col < 192) {
        int h = col >> 4, c = col & 15;
        #pragma unroll
        for (int r = 0; r < PRJ; r++) {
            int row = row0 + r, b = row >> 9, n = row & 511;
            *(float4*)&q_g[((long)(b*HH+h)*NN + n)*CH + c] = acc[r];
        }
    } else if (col < 576) {
        int lc = col - 192;
        int h = lc >> 5, cc = lc & 31;
        #pragma unroll
        for (int r = 0; r < PRJ; r++) {
            int row = row0 + r, b = row >> 9, n = row & 511;
            long base = ((long)(b*HH+h)*NN + n)*CH;
            if (cc < 16) *(float4*)&k_g[base + cc]      = acc[r];
            else         *(float4*)&v_g[base + (cc-16)] = acc[r];
        }
    } else {
        int pc = col - 576;   // 0..575
        #pragma unroll
        for (int r = 0; r < PRJ; r++)
            *(float4*)&psm[RAW_OFF + r*576 + pc] = acc[r];
    }
    __syncthreads();

    // ---- rotation + squared-norm pass (PRJ*192 point-tasks) ----
    for (int pt = tid; pt < PRJ*192; pt += 288) {
        const int r = pt / 192, p = pt % 192;
        const int row = row0 + r, b = row >> 9, n = row & 511;
        const float* raw = psm + RAW_OFF + r*576;
        const float* Rt  = psm + RT_OFF + r*12;
        float d0, d1, d2; int is_qp, h, idx;
        if (p < 48) {        // qp: layout [3][48]
            d0 = raw[p]; d1 = raw[48+p]; d2 = raw[96+p];
            is_qp = 1; h = p >> 2; idx = p & 3;
        } else {             // kvp: layout [3][144] at offset 144
            int pk = p - 48;
            d0 = raw[144+pk]; d1 = raw[288+pk]; d2 = raw[432+pk];
            is_qp = 0; h = pk / 12; idx = pk % 12;
        }
        float x0 = Rt[0]*d0 + Rt[1]*d1 + Rt[2]*d2 + Rt[9];
        float x1 = Rt[3]*d0 + Rt[4]*d1 + Rt[5]*d2 + Rt[10];
        float x2 = Rt[6]*d0 + Rt[7]*d1 + Rt[8]*d2 + Rt[11];
        if (is_qp) {
            long base = ((long)(b*HH+h)*NN + n)*(PQ*3) + idx*3;
            qp_g[base+0] = x0; qp_g[base+1] = x1; qp_g[base+2] = x2;
            atomicAdd(&psm[SQQ_OFF + r*HH + h], x0*x0 + x1*x1 + x2*x2);
        } else if (idx < PQ) {
            long base = ((long)(b*HH+h)*NN + n)*(PQ*3) + idx*3;
            kp_g[base+0] = x0; kp_g[base+1] = x1; kp_g[base+2] = x2;
            atomicAdd(&psm[SQK_OFF + r*HH + h], x0*x0 + x1*x1 + x2*x2);
        } else {
            long base = ((long)(b*HH+h)*NN + n)*(VV*3) + (idx-PQ)*3;
            vp_g[base+0] = x0; vp_g[base+1] = x1; vp_g[base+2] = x2;
        }
    }
    __syncthreads();
    if (tid < PRJ*HH) {
        int r = tid/HH, h = tid%HH;
        int row = row0 + r, b = row >> 9, n = row & 511;
        sqq_g[(long)(b*HH+h)*NN + n] = psm[SQQ_OFF + tid];
        sqk_g[(long)(b*HH+h)*NN + n] = psm[SQK_OFF + tid];
    }
}

// ---------------- kernel 2: attention (R12 version — stable, exact) ----------
#define SKV 20   /* k/v tile stride in floats */
#define SKP 12   /* kp stride */
#define SVP 28   /* vp stride */
#define BUF 4096 /* float offset between buffers */

__global__ __launch_bounds__(256) void attn_kernel(
    const float* __restrict__ pair_mask,
    const float* __restrict__ R, const float* __restrict__ t,
    const float* __restrict__ head_weights)
{
    __shared__ __align__(16) float pool[2*BUF];   // 32 KB, double buffered
    __shared__ float red[8][2][41];

    const int tid  = threadIdx.x;
    const int lane = tid & 31;
    const int warp = tid >> 5;
    const int b = blockIdx.z, h = blockIdx.y;
    const int i0 = blockIdx.x*16 + warp*2;
    const int bh = b*HH + h;

    const float hwv = log1pf(__expf(head_weights[h])) * 0.1360827634879543f; // sqrt(1/54)
    const float c1  = -0.5f * hwv;
    const float qs  = 0.14433756729740643f;  // 1/sqrt(48)

    const float* kbase  = k_g  + (long)bh*NN*CH;
    const float* vbase  = v_g  + (long)bh*NN*CH;
    const float* kpbase = kp_g + (long)bh*NN*12;
    const float* vpbase = vp_g + (long)bh*NN*24;
    const float* sqkrow = sqk_g + (long)bh*NN;
    const float* mrow0  = pair_mask + ((long)b*NN + i0)*NN;
    const float* mrow1  = mrow0 + NN;

    float la0[16], la1[16];

    // ================= phase A: all logits =================
    {
        float q0[CH], q1[CH], qp0[12], qp1[12];
        {
            const float4* qr0 = (const float4*)(q_g + ((long)bh*NN + i0)*CH);
            const float4* qr1 = (const float4*)(q_g + ((long)bh*NN + i0+1)*CH);
            #pragma unroll
            for (int c = 0; c < 4; c++) {
                float4 a = qr0[c];
                q0[4*c]=a.x*qs; q0[4*c+1]=a.y*qs; q0[4*c+2]=a.z*qs; q0[4*c+3]=a.w*qs;
                float4 d = qr1[c];
                q1[4*c]=d.x*qs; q1[4*c+1]=d.y*qs; q1[4*c+2]=d.z*qs; q1[4*c+3]=d.w*qs;
            }
            const float4* pr0 = (const float4*)(qp_g + ((long)bh*NN + i0)*12);
            const float4* pr1 = (const float4*)(qp_g + ((long)bh*NN + i0+1)*12);
            #pragma unroll
            for (int c = 0; c < 3; c++) {
                float4 a = pr0[c];
                qp0[4*c]=a.x*hwv; qp0[4*c+1]=a.y*hwv; qp0[4*c+2]=a.z*hwv; qp0[4*c+3]=a.w*hwv;
                float4 d = pr1[c];
                qp1[4*c]=d.x*hwv; qp1[4*c+1]=d.y*hwv; qp1[4*c+2]=d.z*hwv; qp1[4*c+3]=d.w*hwv;
            }
        }
        const float base0 = c1 * __ldg(&sqq_g[(long)bh*NN + i0]);
        const float base1 = c1 * __ldg(&sqq_g[(long)bh*NN + i0+1]);

        // prologue fill jt=0 -> buf 0
        {
            const float4* k4  = (const float4*)kbase;
            for (int idx = tid; idx < 512; idx += 256)
                __pipeline_memcpy_async(&pool[(idx>>2)*SKV + ((idx&3)<<2)], &k4[idx], 16);
            const float4* kp4 = (const float4*)kpbase;
            for (int idx = tid; idx < 384; idx += 256) {
                int j = idx/3, c = idx - j*3;
                __pipeline_memcpy_async(&pool[2560 + j*SKP + (c<<2)], &kp4[idx], 16);
            }
        }
        __pipeline_commit();

        #pragma unroll
        for (int jt = 0; jt < 4; jt++) {
            if (jt < 3) {
                float* dst = pool + ((jt+1)&1)*BUF;
                const float4* k4  = (const float4*)(kbase + (jt+1)*128*CH);
                for (int idx = tid; idx < 512; idx += 256)
                    __pipeline_memcpy_async(&dst[(idx>>2)*SKV + ((idx&3)<<2)], &k4[idx], 16);
                const float4* kp4 = (const float4*)(kpbase + (jt+1)*128*12);
                for (int idx = tid; idx < 384; idx += 256) {
                    int j = idx/3, c = idx - j*3;
                    __pipeline_memcpy_async(&dst[2560 + j*SKP + (c<<2)], &kp4[idx], 16);
                }
                __pipeline_commit();
                __pipeline_wait_prior(1);
            } else {
                __pipeline_wait_prior(0);
            }
            __syncthreads();

            const float* ks  = pool + (jt&1)*BUF;
            const float* kps = ks + 2560;
            const int j0 = jt*128;
            #pragma unroll
            for (int u = 0; u < 4; u++) {
                const int j = u*32 + lane;
                const float4* k4  = (const float4*)(ks  + j*SKV);
                const float4* kp4 = (const float4*)(kps + j*SKP);
                float qk0 = 0.f, qk1 = 0.f;
                #pragma unroll
                for (int c = 0; c < 4; c++) {
                    float4 kk = k4[c];
                    qk0 += q0[4*c]*kk.x + q0[4*c+1]*kk.y + q0[4*c+2]*kk.z + q0[4*c+3]*kk.w;
                    qk1 += q1[4*c]*kk.x + q1[4*c+1]*kk.y + q1[4*c+2]*kk.z + q1[4*c+3]*kk.w;
                }
                #pragma unroll
                for (int c = 0; c < 3; c++) {
                    float4 kk = kp4[c];
                    qk0 += qp0[4*c]*kk.x + qp0[4*c+1]*kk.y + qp0[4*c+2]*kk.z + qp0[4*c+3]*kk.w;
                    qk1 += qp1[4*c]*kk.x + qp1[4*c+1]*kk.y + qp1[4*c+2]*kk.z + qp1[4*c+3]*kk.w;
                }
                const float skc = c1 * __ldg(&sqkrow[j0 + j]);
                // exact masked offset: fmaf gives exactly 0.0 when mask==1
                const float mq0 = fmaf(__ldg(&mrow0[j0 + j]), 100000.f, -100000.f);
                const float mq1 = fmaf(__ldg(&mrow1[j0 + j]), 100000.f, -100000.f);
                la0[jt*4+u] = qk0 + skc + base0 + mq0;
                la1[jt*4+u] = qk1 + skc + base1 + mq1;
            }
            __syncthreads();
        }
    }

    // ================= exact softmax =================
    float ls0, ls1;
    {
        float M0 = la0[0], M1 = la1[0];
        #pragma unroll
        for (int x = 1; x < 16; x++) { M0 = fmaxf(M0, la0[x]); M1 = fmaxf(M1, la1[x]); }
        #pragma unroll
        for (int o = 16; o; o >>= 1) {
            M0 = fmaxf(M0, __shfl_xor_sync(0xffffffffu, M0, o));
            M1 = fmaxf(M1, __shfl_xor_sync(0xffffffffu, M1, o));
        }
        ls0 = 0.f; ls1 = 0.f;
        #pragma unroll
        for (int x = 0; x < 16; x++) {
            la0[x] = __expf(la0[x] - M0); ls0 += la0[x];
            la1[x] = __expf(la1[x] - M1); ls1 += la1[x];
        }
    }
    __syncthreads();   // phase A tiles dead before B refills pool

    // ================= phase B pass 1: o = A @ v =================
    {
        float av0[16], av1[16];
        #pragma unroll
        for (int x = 0; x < 16; x++) { av0[x] = 0.f; av1[x] = 0.f; }

        {
            const float4* v4 = (const float4*)vbase;
            for (int idx = tid; idx < 512; idx += 256)
                __pipeline_memcpy_async(&pool[(idx>>2)*SKV + ((idx&3)<<2)], &v4[idx], 16);
        }
        __pipeline_commit();

        #pragma unroll
        for (int jt = 0; jt < 4; jt++) {
            if (jt < 3) {
                float* dst = pool + ((jt+1)&1)*BUF;
                const float4* v4 = (const float4*)(vbase + (jt+1)*128*CH);
                for (int idx = tid; idx < 512; idx += 256)
                    __pipeline_memcpy_async(&dst[(idx>>2)*SKV + ((idx&3)<<2)], &v4[idx], 16);
                __pipeline_commit();
                __pipeline_wait_prior(1);
            } else {
                __pipeline_wait_prior(0);
            }
            __syncthreads();

            const float* vs = pool + (jt&1)*BUF;
            #pragma unroll
            for (int u = 0; u < 4; u++) {
                const int j = u*32 + lane;
                const float p0 = la0[jt*4+u];
                const float p1 = la1[jt*4+u];
                const float4* v4 = (const float4*)(vs + j*SKV);
                #pragma unroll
                for (int c = 0; c < 4; c++) {
                    float4 vv = v4[c];
                    av0[4*c]   += p0*vv.x; av0[4*c+1] += p0*vv.y;
                    av0[4*c+2] += p0*vv.z; av0[4*c+3] += p0*vv.w;
                    av1[4*c]   += p1*vv.x; av1[4*c+1] += p1*vv.y;
                    av1[4*c+2] += p1*vv.z; av1[4*c+3] += p1*vv.w;
                }
            }
            __syncthreads();
        }
        float lss = ls0;
        #pragma unroll
        for (int o = 16; o; o >>= 1) lss += __shfl_xor_sync(0xffffffffu, lss, o);
        if (lane == 0) red[warp][0][40] = lss;
        lss = ls1;
        #pragma unroll
        for (int o = 16; o; o >>= 1) lss += __shfl_xor_sync(0xffffffffu, lss, o);
        if (lane == 0) red[warp][1][40] = lss;
        #pragma unroll
        for (int x = 0; x < 16; x++) {
            float v0 = av0[x], v1 = av1[x];
            #pragma unroll
            for (int o = 16; o; o >>= 1) {
                v0 += __shfl_xor_sync(0xffffffffu, v0, o);
                v1 += __shfl_xor_sync(0xffffffffu, v1, o);
            }
            if (lane == 0) { red[warp][0][x] = v0; red[warp][1][x] = v1; }
        }
    }

    // ================= phase B pass 2: o_pt = A @ vp =================
    {
        float ap0[24], ap1[24];
        #pragma unroll
        for (int x = 0; x < 24; x++) { ap0[x] = 0.f; ap1[x] = 0.f; }

        {
            const float4* vp4 = (const float4*)vpbase;
            for (int idx = tid; idx < 768; idx += 256) {
                int j = idx/6, c = idx - j*6;
                __pipeline_memcpy_async(&pool[j*SVP + (c<<2)], &vp4[idx], 16);
            }
        }
        __pipeline_commit();

        #pragma unroll
        for (int jt = 0; jt < 4; jt++) {
            if (jt < 3) {
                float* dst = pool + ((jt+1)&1)*BUF;
                const float4* vp4 = (const float4*)(vpbase + (jt+1)*128*24);
                for (int idx = tid; idx < 768; idx += 256) {
                    int j = idx/6, c = idx - j*6;
                    __pipeline_memcpy_async(&dst[j*SVP + (c<<2)], &vp4[idx], 16);
                }
                __pipeline_commit();
                __pipeline_wait_prior(1);
            } else {
                __pipeline_wait_prior(0);
            }
            __syncthreads();

            const float* vps = pool + (jt&1)*BUF;
            #pragma unroll
            for (int u = 0; u < 4; u++) {
                const int j = u*32 + lane;
                const float p0 = la0[jt*4+u];
                const float p1 = la1[jt*4+u];
                const float4* vp4 = (const float4*)(vps + j*SVP);
                #pragma unroll
                for (int c = 0; c < 6; c++) {
                    float4 vv = vp4[c];
                    ap0[4*c]   += p0*vv.x; ap0[4*c+1] += p0*vv.y;
                    ap0[4*c+2] += p0*vv.z; ap0[4*c+3] += p0*vv.w;
                    ap1[4*c]   += p1*vv.x; ap1[4*c+1] += p1*vv.y;
                    ap1[4*c+2] += p1*vv.z; ap1[4*c+3] += p1*vv.w;
                }
            }
            __syncthreads();
        }
        #pragma unroll
        for (int x = 0; x < 24; x++) {
            float v0 = ap0[x], v1 = ap1[x];
            #pragma unroll
            for (int o = 16; o; o >>= 1) {
                v0 += __shfl_xor_sync(0xffffffffu, v0, o);
                v1 += __shfl_xor_sync(0xffffffffu, v1, o);
            }
            if (lane == 0) { red[warp][0][16+x] = v0; red[warp][1][16+x] = v1; }
        }
    }
    __syncwarp();

    // ================= finalize =================
    #pragma unroll
    for (int ii = 0; ii < 2; ii++) {
        const int i = i0 + ii;
        const float sinv = 1.f / red[warp][ii][40];
        const long rowbase = ((long)(b*NN + i))*CATD;
        if (lane < 16) {
            cat_g[rowbase + h*CH + lane] = red[warp][ii][lane] * sinv;
        } else if (lane < 24) {
            const int vv = lane - 16;
            float gx = red[warp][ii][16 + vv*3 + 0] * sinv;
            float gy = red[warp][ii][16 + vv*3 + 1] * sinv;
            float gz = red[warp][ii][16 + vv*3 + 2] * sinv;
            const float* Rr = R + ((long)(b*NN + i))*9;
            const float* tr = t + ((long)(b*NN + i))*3;
            float lx = Rr[0]*gx + Rr[3]*gy + Rr[6]*gz - tr[0];
            float ly = Rr[1]*gx + Rr[4]*gy + Rr[7]*gz - tr[1];
            float lz = Rr[2]*gx + Rr[5]*gy + Rr[8]*gz - tr[2];
            float nrm = sqrtf(lx*lx + ly*ly + lz*lz + 1e-8f);
            cat_g[rowbase + HC +   0 + h*VV + vv] = lx;
            cat_g[rowbase + HC +  96 + h*VV + vv] = ly;
            cat_g[rowbase + HC + 192 + h*VV + vv] = lz;
            cat_g[rowbase + HC + 288 + h*VV + vv] = nrm;
        }
    }
}

// ---------------- kernel 3: output projection (8 rows/block) -----------------
__global__ __launch_bounds__(256) void out_kernel(
    const float* __restrict__ Wout, const float* __restrict__ bout,
    float* __restrict__ out)
{
    __shared__ float csm[8*CATD];
    const int tid  = threadIdx.x;
    const int col  = tid & 127;
    const int half = tid >> 7;
    const int row0 = blockIdx.x * 8;

    for (int idx = tid; idx < 8*CATD; idx += 256)
        csm[idx] = cat_g[(long)row0*CATD + idx];
    __syncthreads();

    float acc[4] = {0.f, 0.f, 0.f, 0.f};
    const float* cb = csm + half*4*CATD;
    #pragma unroll 8
    for (int k = 0; k < CATD; k++) {
        float w = __ldg(&Wout[(long)k*CS + col]);
        #pragma unroll
        for (int r = 0; r < 4; r++) acc[r] += cb[r*CATD + k] * w;
    }
    float bb = bout[col];
    #pragma unroll
    for (int r = 0; r < 4; r++)
        out[(long)(row0 + half*4 + r)*CS + col] = acc[r] + bb;
}

// ---------------- launcher ----------------------------------------------------
extern "C" void kernel_launch(void* const* d_in, const int* in_sizes, int n_in,
                              void* d_out, int out_size)
{
    const float* s    = (const float*)d_in[0];
    const float* R    = (const float*)d_in[1];
    const float* t    = (const float*)d_in[2];
    const float* mask = (const float*)d_in[3];
    const float* Wq   = (const float*)d_in[4];
    const float* bq   = (const float*)d_in[5];
    const float* Wkv  = (const float*)d_in[6];
    const float* bkv  = (const float*)d_in[7];
    const float* Wqp  = (const float*)d_in[8];
    const float* bqp  = (const float*)d_in[9];
    const float* Wkvp = (const float*)d_in[10];
    const float* bkvp = (const float*)d_in[11];
    const float* hwts = (const float*)d_in[12];
    const float* Wout = (const float*)d_in[13];
    const float* bout = (const float*)d_in[14];
    float* out = (float*)d_out;

    cudaFuncSetAttribute(proj_kernel,
                         cudaFuncAttributeMaxDynamicSharedMemorySize,
                         PROJ_SMEM_BYTES);

    proj_kernel<<<(BB*NN)/PRJ, 288, PROJ_SMEM_BYTES>>>(s, R, t, Wq, bq, Wkv, bkv,
                                                       Wqp, bqp, Wkvp, bkvp);
    attn_kernel<<<dim3(NN/16, HH, BB), 256>>>(mask, R, t, hwts);
    out_kernel<<<(BB*NN)/8, 256>>>(Wout, bout, out);
}

// round 14
// speedup vs baseline: 1.1730x; 1.0198x over previous
#include <cuda_runtime.h>
#include <cuda_pipeline_primitives.h>
#include <math.h>

#define BB 2
#define NN 512
#define CS 128
#define CH 16
#define HH 12
#define PQ 4
#define VV 8
#define HC (HH*CH)            /* 192 */
#define CATD (HH*(CH+VV*4))   /* 576 */

// ---------------- scratch (device globals; no allocations allowed) -----------
__device__ float q_g  [BB*HH*NN*CH];
__device__ float k_g  [BB*HH*NN*CH];
__device__ float v_g  [BB*HH*NN*CH];
__device__ float qp_g [BB*HH*NN*PQ*3];
__device__ float kp_g [BB*HH*NN*PQ*3];
__device__ float vp_g [BB*HH*NN*VV*3];
__device__ float sqq_g[BB*HH*NN];
__device__ float sqk_g[BB*HH*NN];
__device__ float cat_g[BB*NN*CATD];

// ---------------- kernel 1: projections — cp.async W-staged GEMM -------------
// 128 blocks x 288 threads; 8 rows/block; thread owns 4 unified cols (1152 wide).
// W staged in 16 chunks of 8 k-rows, double buffered. Thread-local W tiles:
// each thread fills AND reads only its own 4 columns -> NO barriers in the loop.
#define PRJ 8
#define NCOL 1152
#define S_OFF   0
#define RAW_OFF 1024
#define RT_OFF  5632
#define SQQ_OFF 5728
#define SQK_OFF 5824
#define W_OFF   5952
#define PROJ_SMEM_FLOATS (W_OFF + 2*8*NCOL)
#define PROJ_SMEM_BYTES  (PROJ_SMEM_FLOATS*4)

__global__ __launch_bounds__(288) void proj_kernel(
    const float* __restrict__ s,  const float* __restrict__ R,
    const float* __restrict__ t,
    const float* __restrict__ Wq,  const float* __restrict__ bq,
    const float* __restrict__ Wkv, const float* __restrict__ bkv,
    const float* __restrict__ Wqp, const float* __restrict__ bqp,
    const float* __restrict__ Wkvp,const float* __restrict__ bkvp)
{
    extern __shared__ __align__(16) float psm[];
    const int tid  = threadIdx.x;
    const int row0 = blockIdx.x * PRJ;

    // ---- stage s rows, frames, zero norm accumulators ----
    for (int idx = tid; idx < PRJ*CS/4; idx += 288)
        ((float4*)(psm + S_OFF))[idx] = ((const float4*)s)[(long)row0*32 + idx];
    if (tid < PRJ*12) {
        int r = tid/12, c = tid%12;
        psm[RT_OFF + r*12 + c] =
            (c < 9) ? R[(long)(row0+r)*9 + c] : t[(long)(row0+r)*3 + (c-9)];
    }
    if (tid < PRJ*HH) {
        psm[SQQ_OFF + tid] = 0.f;
        psm[SQK_OFF + tid] = 0.f;
    }

    // ---- column ownership ----
    const int col = tid * 4;           // 0..1148
    const float* Wb; const float* bb; int stride; int lcol;
    if (col < 192)      { Wb = Wq;   bb = bq;   stride = 192; lcol = col;       }
    else if (col < 576) { Wb = Wkv;  bb = bkv;  stride = 384; lcol = col - 192; }
    else if (col < 720) { Wb = Wqp;  bb = bqp;  stride = 144; lcol = col - 576; }
    else                { Wb = Wkvp; bb = bkvp; stride = 432; lcol = col - 720; }

    // ---- prologue: stage W chunk 0 (k = 0..7) ----
    {
        float* dst = psm + W_OFF;
        #pragma unroll
        for (int k = 0; k < 8; k++)
            __pipeline_memcpy_async(&dst[k*NCOL + col], Wb + (long)k*stride + lcol, 16);
    }
    __pipeline_commit();

    const float4 bias4 = __ldg((const float4*)(bb + lcol));
    float4 acc[PRJ];
    #pragma unroll
    for (int r = 0; r < PRJ; r++) acc[r] = bias4;

    __syncthreads();   // s rows staged before use (only barrier before epilogue)

    // ---- main loop: 16 chunks of 8 k; NO barriers (W tiles are thread-local)
    #pragma unroll 4
    for (int ch = 0; ch < 16; ch++) {
        if (ch < 15) {
            float* dst = psm + W_OFF + ((ch+1)&1)*(8*NCOL);
            const long kbase = (long)(ch+1)*8;
            #pragma unroll
            for (int k = 0; k < 8; k++)
                __pipeline_memcpy_async(&dst[k*NCOL + col],
                                        Wb + (kbase+k)*stride + lcol, 16);
            __pipeline_commit();
            __pipeline_wait_prior(1);
        } else {
            __pipeline_wait_prior(0);
        }

        const float* Wc = psm + W_OFF + (ch&1)*(8*NCOL);
        const float4* s4 = (const float4*)(psm + S_OFF);
        #pragma unroll
        for (int kq = 0; kq < 2; kq++) {
            float4 w0 = *(const float4*)&Wc[(kq*4+0)*NCOL + col];
            float4 w1 = *(const float4*)&Wc[(kq*4+1)*NCOL + col];
            float4 w2 = *(const float4*)&Wc[(kq*4+2)*NCOL + col];
            float4 w3 = *(const float4*)&Wc[(kq*4+3)*NCOL + col];
            #pragma unroll
            for (int r = 0; r < PRJ; r++) {
                float4 sv = s4[r*32 + ch*2 + kq];
                acc[r].x += w0.x*sv.x + w1.x*sv.y + w2.x*sv.z + w3.x*sv.w;
                acc[r].y += w0.y*sv.x + w1.y*sv.y + w2.y*sv.z + w3.y*sv.w;
                acc[r].z += w0.z*sv.x + w1.z*sv.y + w2.z*sv.z + w3.z*sv.w;
                acc[r].w += w0.w*sv.x + w1.w*sv.y + w2.w*sv.z + w3.w*sv.w;
            }
        }
    }

    // ---- scatter results ----
    if (col < 192) {
        int h = col >> 4, c = col & 15;
        #pragma unroll
        for (int r = 0; r < PRJ; r++) {
            int row = row0 + r, b = row >> 9, n = row & 511;
            *(float4*)&q_g[((long)(b*HH+h)*NN + n)*CH + c] = acc[r];
        }
    } else if (col < 576) {
        int lc = col - 192;
        int h = lc >> 5, cc = lc & 31;
        #pragma unroll
        for (int r = 0; r < PRJ; r++) {
            int row = row0 + r, b = row >> 9, n = row & 511;
            long base = ((long)(b*HH+h)*NN + n)*CH;
            if (cc < 16) *(float4*)&k_g[base + cc]      = acc[r];
            else         *(float4*)&v_g[base + (cc-16)] = acc[r];
        }
    } else {
        int pc = col - 576;   // 0..575
        #pragma unroll
        for (int r = 0; r < PRJ; r++)
            *(float4*)&psm[RAW_OFF + r*576 + pc] = acc[r];
    }
    __syncthreads();

    // ---- rotation + squared-norm pass (PRJ*192 point-tasks) ----
    for (int pt = tid; pt < PRJ*192; pt += 288) {
        const int r = pt / 192, p = pt % 192;
        const int row = row0 + r, b = row >> 9, n = row & 511;
        const float* raw = psm + RAW_OFF + r*576;
        const float* Rt  = psm + RT_OFF + r*12;
        float d0, d1, d2; int is_qp, h, idx;
        if (p < 48) {        // qp: layout [3][48]
            d0 = raw[p]; d1 = raw[48+p]; d2 = raw[96+p];
            is_qp = 1; h = p >> 2; idx = p & 3;
        } else {             // kvp: layout [3][144] at offset 144
            int pk = p - 48;
            d0 = raw[144+pk]; d1 = raw[288+pk]; d2 = raw[432+pk];
            is_qp = 0; h = pk / 12; idx = pk % 12;
        }
        float x0 = Rt[0]*d0 + Rt[1]*d1 + Rt[2]*d2 + Rt[9];
        float x1 = Rt[3]*d0 + Rt[4]*d1 + Rt[5]*d2 + Rt[10];
        float x2 = Rt[6]*d0 + Rt[7]*d1 + Rt[8]*d2 + Rt[11];
        if (is_qp) {
            long base = ((long)(b*HH+h)*NN + n)*(PQ*3) + idx*3;
            qp_g[base+0] = x0; qp_g[base+1] = x1; qp_g[base+2] = x2;
            atomicAdd(&psm[SQQ_OFF + r*HH + h], x0*x0 + x1*x1 + x2*x2);
        } else if (idx < PQ) {
            long base = ((long)(b*HH+h)*NN + n)*(PQ*3) + idx*3;
            kp_g[base+0] = x0; kp_g[base+1] = x1; kp_g[base+2] = x2;
            atomicAdd(&psm[SQK_OFF + r*HH + h], x0*x0 + x1*x1 + x2*x2);
        } else {
            long base = ((long)(b*HH+h)*NN + n)*(VV*3) + (idx-PQ)*3;
            vp_g[base+0] = x0; vp_g[base+1] = x1; vp_g[base+2] = x2;
        }
    }
    __syncthreads();
    if (tid < PRJ*HH) {
        int r = tid/HH, h = tid%HH;
        int row = row0 + r, b = row >> 9, n = row & 511;
        sqq_g[(long)(b*HH+h)*NN + n] = psm[SQQ_OFF + tid];
        sqk_g[(long)(b*HH+h)*NN + n] = psm[SQK_OFF + tid];
    }
}

// ---------------- kernel 2: attention (R12/R13 version — stable, exact) ------
#define SKV 20   /* k/v tile stride in floats */
#define SKP 12   /* kp stride */
#define SVP 28   /* vp stride */
#define BUF 4096 /* float offset between buffers */

__global__ __launch_bounds__(256) void attn_kernel(
    const float* __restrict__ pair_mask,
    const float* __restrict__ R, const float* __restrict__ t,
    const float* __restrict__ head_weights)
{
    __shared__ __align__(16) float pool[2*BUF];   // 32 KB, double buffered
    __shared__ float red[8][2][41];

    const int tid  = threadIdx.x;
    const int lane = tid & 31;
    const int warp = tid >> 5;
    const int b = blockIdx.z, h = blockIdx.y;
    const int i0 = blockIdx.x*16 + warp*2;
    const int bh = b*HH + h;

    const float hwv = log1pf(__expf(head_weights[h])) * 0.1360827634879543f; // sqrt(1/54)
    const float c1  = -0.5f * hwv;
    const float qs  = 0.14433756729740643f;  // 1/sqrt(48)

    const float* kbase  = k_g  + (long)bh*NN*CH;
    const float* vbase  = v_g  + (long)bh*NN*CH;
    const float* kpbase = kp_g + (long)bh*NN*12;
    const float* vpbase = vp_g + (long)bh*NN*24;
    const float* sqkrow = sqk_g + (long)bh*NN;
    const float* mrow0  = pair_mask + ((long)b*NN + i0)*NN;
    const float* mrow1  = mrow0 + NN;

    float la0[16], la1[16];

    // ================= phase A: all logits =================
    {
        float q0[CH], q1[CH], qp0[12], qp1[12];
        {
            const float4* qr0 = (const float4*)(q_g + ((long)bh*NN + i0)*CH);
            const float4* qr1 = (const float4*)(q_g + ((long)bh*NN + i0+1)*CH);
            #pragma unroll
            for (int c = 0; c < 4; c++) {
                float4 a = qr0[c];
                q0[4*c]=a.x*qs; q0[4*c+1]=a.y*qs; q0[4*c+2]=a.z*qs; q0[4*c+3]=a.w*qs;
                float4 d = qr1[c];
                q1[4*c]=d.x*qs; q1[4*c+1]=d.y*qs; q1[4*c+2]=d.z*qs; q1[4*c+3]=d.w*qs;
            }
            const float4* pr0 = (const float4*)(qp_g + ((long)bh*NN + i0)*12);
            const float4* pr1 = (const float4*)(qp_g + ((long)bh*NN + i0+1)*12);
            #pragma unroll
            for (int c = 0; c < 3; c++) {
                float4 a = pr0[c];
                qp0[4*c]=a.x*hwv; qp0[4*c+1]=a.y*hwv; qp0[4*c+2]=a.z*hwv; qp0[4*c+3]=a.w*hwv;
                float4 d = pr1[c];
                qp1[4*c]=d.x*hwv; qp1[4*c+1]=d.y*hwv; qp1[4*c+2]=d.z*hwv; qp1[4*c+3]=d.w*hwv;
            }
        }
        const float base0 = c1 * __ldg(&sqq_g[(long)bh*NN + i0]);
        const float base1 = c1 * __ldg(&sqq_g[(long)bh*NN + i0+1]);

        // prologue fill jt=0 -> buf 0
        {
            const float4* k4  = (const float4*)kbase;
            for (int idx = tid; idx < 512; idx += 256)
                __pipeline_memcpy_async(&pool[(idx>>2)*SKV + ((idx&3)<<2)], &k4[idx], 16);
            const float4* kp4 = (const float4*)kpbase;
            for (int idx = tid; idx < 384; idx += 256) {
                int j = idx/3, c = idx - j*3;
                __pipeline_memcpy_async(&pool[2560 + j*SKP + (c<<2)], &kp4[idx], 16);
            }
        }
        __pipeline_commit();

        #pragma unroll
        for (int jt = 0; jt < 4; jt++) {
            if (jt < 3) {
                float* dst = pool + ((jt+1)&1)*BUF;
                const float4* k4  = (const float4*)(kbase + (jt+1)*128*CH);
                for (int idx = tid; idx < 512; idx += 256)
                    __pipeline_memcpy_async(&dst[(idx>>2)*SKV + ((idx&3)<<2)], &k4[idx], 16);
                const float4* kp4 = (const float4*)(kpbase + (jt+1)*128*12);
                for (int idx = tid; idx < 384; idx += 256) {
                    int j = idx/3, c = idx - j*3;
                    __pipeline_memcpy_async(&dst[2560 + j*SKP + (c<<2)], &kp4[idx], 16);
                }
                __pipeline_commit();
                __pipeline_wait_prior(1);
            } else {
                __pipeline_wait_prior(0);
            }
            __syncthreads();

            const float* ks  = pool + (jt&1)*BUF;
            const float* kps = ks + 2560;
            const int j0 = jt*128;
            #pragma unroll
            for (int u = 0; u < 4; u++) {
                const int j = u*32 + lane;
                const float4* k4  = (const float4*)(ks  + j*SKV);
                const float4* kp4 = (const float4*)(kps + j*SKP);
                float qk0 = 0.f, qk1 = 0.f;
                #pragma unroll
                for (int c = 0; c < 4; c++) {
                    float4 kk = k4[c];
                    qk0 += q0[4*c]*kk.x + q0[4*c+1]*kk.y + q0[4*c+2]*kk.z + q0[4*c+3]*kk.w;
                    qk1 += q1[4*c]*kk.x + q1[4*c+1]*kk.y + q1[4*c+2]*kk.z + q1[4*c+3]*kk.w;
                }
                #pragma unroll
                for (int c = 0; c < 3; c++) {
                    float4 kk = kp4[c];
                    qk0 += qp0[4*c]*kk.x + qp0[4*c+1]*kk.y + qp0[4*c+2]*kk.z + qp0[4*c+3]*kk.w;
                    qk1 += qp1[4*c]*kk.x + qp1[4*c+1]*kk.y + qp1[4*c+2]*kk.z + qp1[4*c+3]*kk.w;
                }
                const float skc = c1 * __ldg(&sqkrow[j0 + j]);
                const float mq0 = fmaf(__ldg(&mrow0[j0 + j]), 100000.f, -100000.f);
                const float mq1 = fmaf(__ldg(&mrow1[j0 + j]), 100000.f, -100000.f);
                la0[jt*4+u] = qk0 + skc + base0 + mq0;
                la1[jt*4+u] = qk1 + skc + base1 + mq1;
            }
            __syncthreads();
        }
    }

    // ================= exact softmax =================
    float ls0, ls1;
    {
        float M0 = la0[0], M1 = la1[0];
        #pragma unroll
        for (int x = 1; x < 16; x++) { M0 = fmaxf(M0, la0[x]); M1 = fmaxf(M1, la1[x]); }
        #pragma unroll
        for (int o = 16; o; o >>= 1) {
            M0 = fmaxf(M0, __shfl_xor_sync(0xffffffffu, M0, o));
            M1 = fmaxf(M1, __shfl_xor_sync(0xffffffffu, M1, o));
        }
        ls0 = 0.f; ls1 = 0.f;
        #pragma unroll
        for (int x = 0; x < 16; x++) {
            la0[x] = __expf(la0[x] - M0); ls0 += la0[x];
            la1[x] = __expf(la1[x] - M1); ls1 += la1[x];
        }
    }
    __syncthreads();   // phase A tiles dead before B refills pool

    // ================= phase B pass 1: o = A @ v =================
    {
        float av0[16], av1[16];
        #pragma unroll
        for (int x = 0; x < 16; x++) { av0[x] = 0.f; av1[x] = 0.f; }

        {
            const float4* v4 = (const float4*)vbase;
            for (int idx = tid; idx < 512; idx += 256)
                __pipeline_memcpy_async(&pool[(idx>>2)*SKV + ((idx&3)<<2)], &v4[idx], 16);
        }
        __pipeline_commit();

        #pragma unroll
        for (int jt = 0; jt < 4; jt++) {
            if (jt < 3) {
                float* dst = pool + ((jt+1)&1)*BUF;
                const float4* v4 = (const float4*)(vbase + (jt+1)*128*CH);
                for (int idx = tid; idx < 512; idx += 256)
                    __pipeline_memcpy_async(&dst[(idx>>2)*SKV + ((idx&3)<<2)], &v4[idx], 16);
                __pipeline_commit();
                __pipeline_wait_prior(1);
            } else {
                __pipeline_wait_prior(0);
            }
            __syncthreads();

            const float* vs = pool + (jt&1)*BUF;
            #pragma unroll
            for (int u = 0; u < 4; u++) {
                const int j = u*32 + lane;
                const float p0 = la0[jt*4+u];
                const float p1 = la1[jt*4+u];
                const float4* v4 = (const float4*)(vs + j*SKV);
                #pragma unroll
                for (int c = 0; c < 4; c++) {
                    float4 vv = v4[c];
                    av0[4*c]   += p0*vv.x; av0[4*c+1] += p0*vv.y;
                    av0[4*c+2] += p0*vv.z; av0[4*c+3] += p0*vv.w;
                    av1[4*c]   += p1*vv.x; av1[4*c+1] += p1*vv.y;
                    av1[4*c+2] += p1*vv.z; av1[4*c+3] += p1*vv.w;
                }
            }
            __syncthreads();
        }
        float lss = ls0;
        #pragma unroll
        for (int o = 16; o; o >>= 1) lss += __shfl_xor_sync(0xffffffffu, lss, o);
        if (lane == 0) red[warp][0][40] = lss;
        lss = ls1;
        #pragma unroll
        for (int o = 16; o; o >>= 1) lss += __shfl_xor_sync(0xffffffffu, lss, o);
        if (lane == 0) red[warp][1][40] = lss;
        #pragma unroll
        for (int x = 0; x < 16; x++) {
            float v0 = av0[x], v1 = av1[x];
            #pragma unroll
            for (int o = 16; o; o >>= 1) {
                v0 += __shfl_xor_sync(0xffffffffu, v0, o);
                v1 += __shfl_xor_sync(0xffffffffu, v1, o);
            }
            if (lane == 0) { red[warp][0][x] = v0; red[warp][1][x] = v1; }
        }
    }

    // ================= phase B pass 2: o_pt = A @ vp =================
    {
        float ap0[24], ap1[24];
        #pragma unroll
        for (int x = 0; x < 24; x++) { ap0[x] = 0.f; ap1[x] = 0.f; }

        {
            const float4* vp4 = (const float4*)vpbase;
            for (int idx = tid; idx < 768; idx += 256) {
                int j = idx/6, c = idx - j*6;
                __pipeline_memcpy_async(&pool[j*SVP + (c<<2)], &vp4[idx], 16);
            }
        }
        __pipeline_commit();

        #pragma unroll
        for (int jt = 0; jt < 4; jt++) {
            if (jt < 3) {
                float* dst = pool + ((jt+1)&1)*BUF;
                const float4* vp4 = (const float4*)(vpbase + (jt+1)*128*24);
                for (int idx = tid; idx < 768; idx += 256) {
                    int j = idx/6, c = idx - j*6;
                    __pipeline_memcpy_async(&dst[j*SVP + (c<<2)], &vp4[idx], 16);
                }
                __pipeline_commit();
                __pipeline_wait_prior(1);
            } else {
                __pipeline_wait_prior(0);
            }
            __syncthreads();

            const float* vps = pool + (jt&1)*BUF;
            #pragma unroll
            for (int u = 0; u < 4; u++) {
                const int j = u*32 + lane;
                const float p0 = la0[jt*4+u];
                const float p1 = la1[jt*4+u];
                const float4* vp4 = (const float4*)(vps + j*SVP);
                #pragma unroll
                for (int c = 0; c < 6; c++) {
                    float4 vv = vp4[c];
                    ap0[4*c]   += p0*vv.x; ap0[4*c+1] += p0*vv.y;
                    ap0[4*c+2] += p0*vv.z; ap0[4*c+3] += p0*vv.w;
                    ap1[4*c]   += p1*vv.x; ap1[4*c+1] += p1*vv.y;
                    ap1[4*c+2] += p1*vv.z; ap1[4*c+3] += p1*vv.w;
                }
            }
            __syncthreads();
        }
        #pragma unroll
        for (int x = 0; x < 24; x++) {
            float v0 = ap0[x], v1 = ap1[x];
            #pragma unroll
            for (int o = 16; o; o >>= 1) {
                v0 += __shfl_xor_sync(0xffffffffu, v0, o);
                v1 += __shfl_xor_sync(0xffffffffu, v1, o);
            }
            if (lane == 0) { red[warp][0][16+x] = v0; red[warp][1][16+x] = v1; }
        }
    }
    __syncwarp();

    // ================= finalize =================
    #pragma unroll
    for (int ii = 0; ii < 2; ii++) {
        const int i = i0 + ii;
        const float sinv = 1.f / red[warp][ii][40];
        const long rowbase = ((long)(b*NN + i))*CATD;
        if (lane < 16) {
            cat_g[rowbase + h*CH + lane] = red[warp][ii][lane] * sinv;
        } else if (lane < 24) {
            const int vv = lane - 16;
            float gx = red[warp][ii][16 + vv*3 + 0] * sinv;
            float gy = red[warp][ii][16 + vv*3 + 1] * sinv;
            float gz = red[warp][ii][16 + vv*3 + 2] * sinv;
            const float* Rr = R + ((long)(b*NN + i))*9;
            const float* tr = t + ((long)(b*NN + i))*3;
            float lx = Rr[0]*gx + Rr[3]*gy + Rr[6]*gz - tr[0];
            float ly = Rr[1]*gx + Rr[4]*gy + Rr[7]*gz - tr[1];
            float lz = Rr[2]*gx + Rr[5]*gy + Rr[8]*gz - tr[2];
            float nrm = sqrtf(lx*lx + ly*ly + lz*lz + 1e-8f);
            cat_g[rowbase + HC +   0 + h*VV + vv] = lx;
            cat_g[rowbase + HC +  96 + h*VV + vv] = ly;
            cat_g[rowbase + HC + 192 + h*VV + vv] = lz;
            cat_g[rowbase + HC + 288 + h*VV + vv] = nrm;
        }
    }
}

// ---------------- kernel 3: output projection (8 rows/block) -----------------
__global__ __launch_bounds__(256) void out_kernel(
    const float* __restrict__ Wout, const float* __restrict__ bout,
    float* __restrict__ out)
{
    __shared__ float csm[8*CATD];
    const int tid  = threadIdx.x;
    const int col  = tid & 127;
    const int half = tid >> 7;
    const int row0 = blockIdx.x * 8;

    for (int idx = tid; idx < 8*CATD; idx += 256)
        csm[idx] = cat_g[(long)row0*CATD + idx];
    __syncthreads();

    float acc[4] = {0.f, 0.f, 0.f, 0.f};
    const float* cb = csm + half*4*CATD;
    #pragma unroll 8
    for (int k = 0; k < CATD; k++) {
        float w = __ldg(&Wout[(long)k*CS + col]);
        #pragma unroll
        for (int r = 0; r < 4; r++) acc[r] += cb[r*CATD + k] * w;
    }
    float bb = bout[col];
    #pragma unroll
    for (int r = 0; r < 4; r++)
        out[(long)(row0 + half*4 + r)*CS + col] = acc[r] + bb;
}

// ---------------- launcher ----------------------------------------------------
extern "C" void kernel_launch(void* const* d_in, const int* in_sizes, int n_in,
                              void* d_out, int out_size)
{
    const float* s    = (const float*)d_in[0];
    const float* R    = (const float*)d_in[1];
    const float* t    = (const float*)d_in[2];
    const float* mask = (const float*)d_in[3];
    const float* Wq   = (const float*)d_in[4];
    const float* bq   = (const float*)d_in[5];
    const float* Wkv  = (const float*)d_in[6];
    const float* bkv  = (const float*)d_in[7];
    const float* Wqp  = (const float*)d_in[8];
    const float* bqp  = (const float*)d_in[9];
    const float* Wkvp = (const float*)d_in[10];
    const float* bkvp = (const float*)d_in[11];
    const float* hwts = (const float*)d_in[12];
    const float* Wout = (const float*)d_in[13];
    const float* bout = (const float*)d_in[14];
    float* out = (float*)d_out;

    cudaFuncSetAttribute(proj_kernel,
                         cudaFuncAttributeMaxDynamicSharedMemorySize,
                         PROJ_SMEM_BYTES);

    proj_kernel<<<(BB*NN)/PRJ, 288, PROJ_SMEM_BYTES>>>(s, R, t, Wq, bq, Wkv, bkv,
                                                       Wqp, bqp, Wkvp, bkvp);
    attn_kernel<<<dim3(NN/16, HH, BB), 256>>>(mask, R, t, hwts);
    out_kernel<<<(BB*NN)/8, 256>>>(Wout, bout, out);
}